// round 7
// baseline (speedup 1.0000x reference)
#include <cuda_runtime.h>
#include <cstdint>

#define NB   32
#define NH   64
#define NW   64
#define HO   62
#define WO   62
#define NPB  (HO*WO)            // 3844
#define NCTA 296                // persistent grid: 148 SMs x 2
#define NUNIT 992               // 31 ho-tiles x 32 batches

// packed fp16 x: word = (ch even lo, ch odd hi); layout [b][c2 32][h][w], +pad
__device__ __align__(16) uint32_t g_x16[NB*32*NH*NW + 16];   // 16.78 MB
// A: [g 12][kw 3][oc 128][slot 8] fp16x2
__device__ __align__(16) uint32_t g_a16[36*1024];            // 147.5 KB

// ---- SMEM geometry (words per buffer) ----
#define AWRD  3072              // 3 kw tiles x 128 oc x 8 slots
#define BWRD  1088              // 8 c2 x 2 rows x 68
#define STW   (AWRD + BWRD)     // 4160
#define NBUF  3
#define SMEMB (NBUF*STW*4)      // 49920 B

// ---------------- PTX helpers ----------------
__device__ __forceinline__ uint32_t cvta_s(const void* p) {
    uint32_t a;
    asm("{ .reg .u64 t; cvta.to.shared.u64 t, %1; cvt.u32.u64 %0, t; }" : "=r"(a) : "l"(p));
    return a;
}
__device__ __forceinline__ uint32_t pack_h2(float even, float odd) {
    uint32_t d;
    asm("cvt.rn.f16x2.f32 %0, %1, %2;" : "=r"(d) : "f"(odd), "f"(even));
    return d;
}
__device__ __forceinline__ uint2 lds64(uint32_t addr) {
    uint2 v;
    asm volatile("ld.shared.v2.b32 {%0,%1},[%2];" : "=r"(v.x), "=r"(v.y) : "r"(addr));
    return v;
}
__device__ __forceinline__ uint32_t lds32(uint32_t addr) {
    uint32_t v;
    asm volatile("ld.shared.b32 %0,[%1];" : "=r"(v) : "r"(addr));
    return v;
}
#define CP_A16(dst, src) asm volatile("cp.async.cg.shared.global [%0],[%1],16;" :: "r"(dst), "l"(src))
#define CP_COMMIT()      asm volatile("cp.async.commit_group;" ::: "memory")
#define CP_WAIT0()       asm volatile("cp.async.wait_group 0;" ::: "memory")
#define CP_WAIT1()       asm volatile("cp.async.wait_group 1;" ::: "memory")

__device__ __forceinline__ void mma_f16(float* c, const uint32_t* a, const uint32_t* b) {
    asm volatile(
        "mma.sync.aligned.m16n8k16.row.col.f32.f16.f16.f32 "
        "{%0,%1,%2,%3},{%4,%5,%6,%7},{%8,%9},{%0,%1,%2,%3};"
        : "+f"(c[0]), "+f"(c[1]), "+f"(c[2]), "+f"(c[3])
        : "r"(a[0]), "r"(a[1]), "r"(a[2]), "r"(a[3]), "r"(b[0]), "r"(b[1]));
}

// ---------------- prep kernels ----------------
__global__ void prep_x16(const float* __restrict__ x) {
    int t = blockIdx.x * 256 + threadIdx.x;      // 1,048,576
    int b    = t >> 15;
    int r    = t & 32767;
    int c2   = r >> 10;
    int pos4 = r & 1023;
    const float4* pe = (const float4*)(x + ((size_t)b * 64 + 2*c2)     * (NH*NW)) + pos4;
    const float4* po = (const float4*)(x + ((size_t)b * 64 + 2*c2 + 1) * (NH*NW)) + pos4;
    float4 e = *pe, o = *po;
    uint4 d;
    d.x = pack_h2(e.x, o.x);
    d.y = pack_h2(e.y, o.y);
    d.z = pack_h2(e.z, o.z);
    d.w = pack_h2(e.w, o.w);
    ((uint4*)g_x16)[((size_t)b * 32 + c2) * 1024 + pos4] = d;
}

__global__ void prep_w(const float* __restrict__ w) {
    int idx = blockIdx.x * 256 + threadIdx.x;    // 36864
    int slot = idx & 7;
    int oc   = (idx >> 3) & 127;
    int sA   = idx >> 10;          // 0..35 = g*3 + kw
    int g    = sA / 3;
    int kw   = sA - g * 3;
    int kh   = g >> 2;
    int cblk = g & 3;
    int off  = kh * 3 + kw;
    int p    = (slot >> 1) + 4 * (slot & 1);
    int ce   = cblk * 16 + 2 * p;
    g_a16[idx] = pack_h2(w[oc * 576 + ce * 9 + off], w[oc * 576 + (ce + 1) * 9 + off]);
}

// ---------------- main kernel ----------------
__global__ __launch_bounds__(256, 2) void conv_main(float* __restrict__ out) {
    extern __shared__ __align__(16) uint32_t sm[];

    const int tid  = threadIdx.x;
    const int lane = tid & 31;
    const int warp = tid >> 5;
    const int wm   = warp >> 2;        // 0..1 : oc half
    const int wn   = warp & 3;
    const int rW   = wn >> 1;          // output row within tile
    const int cW   = (wn & 1) * 32;    // wo base

    const int cta = blockIdx.x;
    const int nu  = (cta < (NUNIT - 3 * NCTA)) ? 4 : 3;   // 992 = 296*3 + 104
    const int S   = nu * 12;

    const uint32_t smem_b = cvta_s(sm);

    // ---- fixed B staging descriptors (word offsets) ----
    uint32_t bd0, bs0, bd1 = 0, bs1 = 0;
    {
        int i = tid, run = i / 17, q = i - run * 17;
        int c2 = run >> 1, r = run & 1;
        bd0 = (uint32_t)(AWRD + c2 * 136 + r * 68 + q * 4);
        bs0 = (uint32_t)(c2 * 4096 + r * 64 + q * 4);
        if (tid < 16) {
            int i2 = 256 + tid, run2 = i2 / 17, q2 = i2 - run2 * 17;
            int c22 = run2 >> 1, r2 = run2 & 1;
            bd1 = (uint32_t)(AWRD + c22 * 136 + r2 * 68 + q2 * 4);
            bs1 = (uint32_t)(c22 * 4096 + r2 * 64 + q2 * 4);
        }
    }

    // ---- issue-side state ----
    int gi = 0;
    int ui = cta;
    const uint32_t* bi = g_x16 + (size_t)(ui & 31) * (32*NH*NW) + (size_t)(ui >> 5) * 128;
    uint32_t ibuf = 0;

    auto issue = [&]() {
        const int kh   = gi >> 2;
        const int cblk = gi & 3;
        const uint4* asrc = (const uint4*)(g_a16 + gi * AWRD) + tid;
        const uint32_t adst = smem_b + ibuf * 4 + (uint32_t)tid * 16;
        CP_A16(adst,        asrc);
        CP_A16(adst + 4096, asrc + 256);
        CP_A16(adst + 8192, asrc + 512);
        const uint32_t soff = (uint32_t)(cblk * 8 * 4096 + kh * 64);
        CP_A16(smem_b + (ibuf + bd0) * 4, (const char*)(bi + bs0 + soff));
        if (tid < 16)
            CP_A16(smem_b + (ibuf + bd1) * 4, (const char*)(bi + bs1 + soff));
        CP_COMMIT();
        if (++gi == 12) {
            gi = 0;
            ui += NCTA;
            bi = g_x16 + (size_t)(ui & 31) * (32*NH*NW) + (size_t)(ui >> 5) * 128;
        }
        ibuf += STW; if (ibuf == NBUF * STW) ibuf = 0;
    };

    issue();
    issue();

    // ---- compute-side state ----
    int gc = 0;
    int uc = cta;
    uint32_t cbuf = 0;

    float acc[4][4][4];
    #pragma unroll
    for (int mi = 0; mi < 4; ++mi)
        #pragma unroll
        for (int ni = 0; ni < 4; ++ni)
            #pragma unroll
            for (int q = 0; q < 4; ++q) acc[mi][ni][q] = 0.0f;

    const uint32_t a_fw = ((uint32_t)(wm * 64 + (lane >> 2)) * 8 + (lane & 3) * 2) * 4;
    const uint32_t b_fw = (uint32_t)(AWRD + (lane & 3) * 136 + rW * 68 + cW + (lane >> 2)) * 4;

    #pragma unroll 1
    for (int s = 0; s < S; ++s) {
        if (s == S - 1) { CP_WAIT0(); } else { CP_WAIT1(); }
        __syncthreads();
        if (s + 2 < S) issue();

        const uint32_t abase0 = smem_b + cbuf * 4 + a_fw;
        const uint32_t bbase0 = smem_b + cbuf * 4 + b_fw;

        #pragma unroll
        for (int kw = 0; kw < 3; ++kw) {
            const uint32_t abase = abase0 + (uint32_t)kw * 4096;
            const uint32_t bbase = bbase0 + (uint32_t)kw * 4;

            uint32_t af[4][4], bf[4][2];
            #pragma unroll
            for (int mi = 0; mi < 4; ++mi) {
                uint2 t0 = lds64(abase + (uint32_t)mi * 512);
                uint2 t1 = lds64(abase + (uint32_t)(mi * 512 + 256));
                af[mi][0] = t0.x; af[mi][1] = t1.x; af[mi][2] = t0.y; af[mi][3] = t1.y;
            }
            #pragma unroll
            for (int ni = 0; ni < 4; ++ni) {
                bf[ni][0] = lds32(bbase + (uint32_t)ni * 32);
                bf[ni][1] = lds32(bbase + (uint32_t)ni * 32 + 2176);
            }
            #pragma unroll
            for (int mi = 0; mi < 4; ++mi)
                #pragma unroll
                for (int ni = 0; ni < 4; ++ni)
                    mma_f16(acc[mi][ni], af[mi], bf[ni]);
        }

        if (gc == 11) {
            // ---- epilogue for unit uc ----
            const int b_c  = uc & 31;
            const int orow = (uc >> 5) * 2 + rW;
            #pragma unroll
            for (int mi = 0; mi < 4; ++mi) {
                #pragma unroll
                for (int ni = 0; ni < 4; ++ni) {
                    const int ocr = wm * 64 + mi * 16 + (lane >> 2);
                    const int wo  = cW + ni * 8 + 2 * (lane & 3);
                    if (wo < WO) {
                        const size_t base = (size_t)orow * WO + wo;
                        float* p0 = out + ((size_t)ocr * NB + b_c) * NPB + base;
                        *(float2*)p0 = make_float2(acc[mi][ni][0], acc[mi][ni][1]);
                        float* p1 = out + ((size_t)(ocr + 8) * NB + b_c) * NPB + base;
                        *(float2*)p1 = make_float2(acc[mi][ni][2], acc[mi][ni][3]);
                    }
                }
            }
            #pragma unroll
            for (int mi = 0; mi < 4; ++mi)
                #pragma unroll
                for (int ni = 0; ni < 4; ++ni)
                    #pragma unroll
                    for (int q = 0; q < 4; ++q) acc[mi][ni][q] = 0.0f;
            gc = 0;
            uc += NCTA;
        } else {
            ++gc;
        }

        cbuf += STW; if (cbuf == NBUF * STW) cbuf = 0;
    }
}

// ---------------- launch ----------------
extern "C" void kernel_launch(void* const* d_in, const int* in_sizes, int n_in,
                              void* d_out, int out_size) {
    const float* x = (const float*)d_in[0];
    const float* w = (const float*)d_in[1];
    float* out = (float*)d_out;

    cudaFuncSetAttribute(conv_main, cudaFuncAttributeMaxDynamicSharedMemorySize, SMEMB);

    prep_x16<<<4096, 256>>>(x);
    prep_w<<<144, 256>>>(w);
    conv_main<<<NCTA, 256, SMEMB>>>(out);
}